// round 10
// baseline (speedup 1.0000x reference)
#include <cuda_runtime.h>
#include <cstdint>

// Shapes fixed by setup_inputs: n=16384, C=32, G=128, N=200000
#define Gdim 128
#define Cdim 32
#define NTHREADS 128
#define NWARPS 4
#define NPW 8               // neighbors per warp
#define INV_SIGMA 10.0f
#define ROW_BYTES 512
#define TILE_BYTES (Cdim * ROW_BYTES)   // 16384

typedef unsigned long long u64;

// ---- packed f32x2 helpers (sm_103a) ----
__device__ __forceinline__ u64 pack2(float lo, float hi) {
    u64 r; asm("mov.b64 %0, {%1, %2};" : "=l"(r) : "f"(lo), "f"(hi)); return r;
}
__device__ __forceinline__ void unpack2(u64 a, float& lo, float& hi) {
    asm("mov.b64 {%0, %1}, %2;" : "=f"(lo), "=f"(hi) : "l"(a));
}
__device__ __forceinline__ u64 add2(u64 a, u64 b) {
    u64 r; asm("add.rn.f32x2 %0, %1, %2;" : "=l"(r) : "l"(a), "l"(b)); return r;
}
__device__ __forceinline__ u64 mul2(u64 a, u64 b) {
    u64 r; asm("mul.rn.f32x2 %0, %1, %2;" : "=l"(r) : "l"(a), "l"(b)); return r;
}
__device__ __forceinline__ u64 fma2(u64 a, u64 b, u64 c) {
    u64 r; asm("fma.rn.f32x2 %0, %1, %2, %3;" : "=l"(r) : "l"(a), "l"(b), "l"(c)); return r;
}

// Butterfly reduce-scatter of 8 per-lane values over 32 lanes: 9 shuffles.
// On return every lane's vals[0] holds the warp total of value index
//   j = ((lane>>4)&1)<<2 | ((lane>>3)&1)<<1 | ((lane>>2)&1).
__device__ __forceinline__ float butterfly8(float* vals, int lane) {
    if (lane & 16) {
        #pragma unroll
        for (int i = 0; i < 4; ++i) { float t = vals[i]; vals[i] = vals[i + 4]; vals[i + 4] = t; }
    }
    #pragma unroll
    for (int i = 0; i < 4; ++i) vals[i] += __shfl_xor_sync(0xffffffffu, vals[i + 4], 16);
    if (lane & 8) {
        #pragma unroll
        for (int i = 0; i < 2; ++i) { float t = vals[i]; vals[i] = vals[i + 2]; vals[i + 2] = t; }
    }
    #pragma unroll
    for (int i = 0; i < 2; ++i) vals[i] += __shfl_xor_sync(0xffffffffu, vals[i + 2], 8);
    if (lane & 4) { float t = vals[0]; vals[0] = vals[1]; vals[1] = t; }
    vals[0] += __shfl_xor_sync(0xffffffffu, vals[1], 4);
    vals[0] += __shfl_xor_sync(0xffffffffu, vals[0], 2);
    vals[0] += __shfl_xor_sync(0xffffffffu, vals[0], 1);
    return vals[0];
}

__global__ __launch_bounds__(NTHREADS, 10)
void nc_kernel(const float* __restrict__ x,
               const float* __restrict__ v,
               const void*  __restrict__ kidx,
               const float* __restrict__ X,
               float* __restrict__ out)
{
    __shared__ __align__(128) char s_rows[Cdim][ROW_BYTES];   // 16 KB gather tile
    __shared__ float s_part[NWARPS][Gdim];                     // 2 KB
    __shared__ float s_num[Cdim];
    __shared__ float s_d2[Cdim];
    __shared__ u64   s_mbar;

    const int row  = blockIdx.x;
    const int tid  = threadIdx.x;
    const int wid  = tid >> 5;
    const int lane = tid & 31;

    const unsigned int mbar = (unsigned int)__cvta_generic_to_shared(&s_mbar);

    if (tid == 0) {
        asm volatile("mbarrier.init.shared.b64 [%0], %1;" :: "r"(mbar), "r"(1) : "memory");
    }
    __syncthreads();

    // Warp 0: detect k dtype, load one index per lane, issue 32 bulk copies
    // (one 512B X row each) against the mbarrier.
    if (wid == 0) {
        // If k is int64 (LE, values < 200000), words 1,3,..,15 of the first
        // 64B are all zero. FP probability for int32 data: (1/2e5)^8 ~ 0.
        const unsigned int w0 = reinterpret_cast<const unsigned int*>(kidx)[lane & 15];
        const unsigned int nz = __ballot_sync(0xffffffffu, (lane < 16) && (lane & 1) && (w0 != 0u));
        const int k64 = (nz == 0u);

        long long idx;
        if (k64) idx = reinterpret_cast<const long long*>(kidx)[(size_t)row * Cdim + lane];
        else     idx = (long long)reinterpret_cast<const int*>(kidx)[(size_t)row * Cdim + lane];

        if (lane == 0) {
            asm volatile("mbarrier.arrive.expect_tx.shared.b64 _, [%0], %1;"
                         :: "r"(mbar), "r"((unsigned int)TILE_BYTES) : "memory");
        }
        __syncwarp();

        const unsigned int dst = (unsigned int)__cvta_generic_to_shared(&s_rows[lane][0]);
        const char* src = reinterpret_cast<const char*>(X) + ((size_t)idx << 9);
        asm volatile(
            "cp.async.bulk.shared::cta.global.mbarrier::complete_tx::bytes [%0], [%1], %2, [%3];"
            :: "r"(dst), "l"(src), "r"((unsigned int)ROW_BYTES), "r"(mbar) : "memory");
    }

    // Overlapped with the DMA: x,v rows + 1/||v|| (per-warp redundant).
    const float4 xv = reinterpret_cast<const float4*>(x + (size_t)row * Gdim)[lane];
    const float4 vv = reinterpret_cast<const float4*>(v + (size_t)row * Gdim)[lane];

    const u64 v01  = pack2(vv.x, vv.y), v23  = pack2(vv.z, vv.w);
    const u64 nx01 = pack2(-xv.x, -xv.y), nx23 = pack2(-xv.z, -xv.w);

    float rvnorm;
    {
        float ss = vv.x * vv.x + vv.y * vv.y + vv.z * vv.z + vv.w * vv.w;
        #pragma unroll
        for (int o = 16; o; o >>= 1)
            ss += __shfl_xor_sync(0xffffffffu, ss, o);
        rvnorm = rsqrtf(ss);
    }

    // Wait for all 16 KB to land (phase parity 0; fresh barrier each launch).
    {
        asm volatile(
            "{\n\t"
            ".reg .pred P1;\n\t"
            "WAIT_%=:\n\t"
            "mbarrier.try_wait.parity.acquire.cta.shared::cta.b64 P1, [%0], 0;\n\t"
            "@!P1 bra WAIT_%=;\n\t"
            "}"
            :: "r"(mbar) : "memory");
    }

    // Read this warp's 8 rows from smem (29-cyc hits), deltas in f32x2 regs.
    u64 d01[NPW], d23[NPW];
    #pragma unroll
    for (int j = 0; j < NPW; ++j) {
        const float4 Xl = *reinterpret_cast<const float4*>(&s_rows[wid * NPW + j][lane << 4]);
        d01[j] = add2(pack2(Xl.x, Xl.y), nx01);
        d23[j] = add2(pack2(Xl.z, Xl.w), nx23);
    }

    // Pass 1: num_j = dot(v, delta_j), butterfly, publish.
    {
        float nums[NPW];
        #pragma unroll
        for (int j = 0; j < NPW; ++j) {
            u64 p = fma2(d23[j], v23, mul2(d01[j], v01));
            float lo, hi; unpack2(p, lo, hi);
            nums[j] = lo + hi;
        }
        const float r = butterfly8(nums, lane);
        if ((lane & 3) == 0) {
            const int j = (((lane >> 4) & 1) << 2) | (((lane >> 3) & 1) << 1) | ((lane >> 2) & 1);
            s_num[wid * NPW + j] = r;
        }
    }
    // Pass 2: d2_j = ||delta_j||^2, butterfly, publish.
    {
        float d2s[NPW];
        #pragma unroll
        for (int j = 0; j < NPW; ++j) {
            u64 q = fma2(d23[j], d23[j], mul2(d01[j], d01[j]));
            float lo, hi; unpack2(q, lo, hi);
            d2s[j] = lo + hi;
        }
        const float r = butterfly8(d2s, lane);
        if ((lane & 3) == 0) {
            const int j = (((lane >> 4) & 1) << 2) | (((lane >> 3) & 1) << 1) | ((lane >> 2) & 1);
            s_d2[wid * NPW + j] = r;
        }
    }
    __syncthreads();

    // Weights, redundantly per warp (lane l = neighbor l), fast math.
    float wl;
    {
        const float d2 = fmaxf(s_d2[lane], 1e-24f);
        const float cs = s_num[lane] * rsqrtf(d2) * rvnorm;
        const float tv = __expf(cs * INV_SIGMA) - 1.0f;
        // reduce-scatter of (sum|tv|, sum tv): 6 shuffles + 1 exchange.
        const float sa = fabsf(tv);
        float keep = (lane & 16) ? tv : sa;
        float send = (lane & 16) ? sa : tv;
        keep += __shfl_xor_sync(0xffffffffu, send, 16);
        keep += __shfl_xor_sync(0xffffffffu, keep, 8);
        keep += __shfl_xor_sync(0xffffffffu, keep, 4);
        keep += __shfl_xor_sync(0xffffffffu, keep, 2);
        keep += __shfl_xor_sync(0xffffffffu, keep, 1);
        const float other = __shfl_xor_sync(0xffffffffu, keep, 16);
        const float sa_t = (lane & 16) ? other : keep;
        const float st_t = (lane & 16) ? keep  : other;
        wl = (tv - st_t * (1.0f / (float)Cdim)) * __fdividef(1.0f, sa_t);
    }

    // Warp partial: sum_j w_j * delta_j  (packed FMA, regs -> smem)
    {
        u64 acc01 = 0ull, acc23 = 0ull;
        #pragma unroll
        for (int j = 0; j < NPW; ++j) {
            const float wj = __shfl_sync(0xffffffffu, wl, wid * NPW + j);
            const u64 w2 = pack2(wj, wj);
            acc01 = fma2(w2, d01[j], acc01);
            acc23 = fma2(w2, d23[j], acc23);
        }
        float4 a;
        unpack2(acc01, a.x, a.y);
        unpack2(acc23, a.z, a.w);
        reinterpret_cast<float4*>(s_part[wid])[lane] = a;
    }
    __syncthreads();

    // Reduce 4 warp partials (128 threads, one g each), coalesced store.
    {
        float r = (s_part[0][tid] + s_part[1][tid]) + (s_part[2][tid] + s_part[3][tid]);
        out[(size_t)row * Gdim + tid] = r;
    }
}

extern "C" void kernel_launch(void* const* d_in, const int* in_sizes, int n_in,
                              void* d_out, int out_size) {
    const float* x = (const float*)d_in[0];
    const float* v = (const float*)d_in[1];
    const void*  k = d_in[2];
    const float* X = (const float*)d_in[3];
    float* out = (float*)d_out;

    const int n = in_sizes[0] / Gdim;   // 16384

    nc_kernel<<<n, NTHREADS>>>(x, v, k, X, out);
}

// round 12
// speedup vs baseline: 1.2600x; 1.2600x over previous
#include <cuda_runtime.h>

// Shapes fixed by setup_inputs: n=16384, C=32, G=128, N=200000
#define Gdim 128
#define Cdim 32
#define NTHREADS 128
#define NWARPS 4
#define NPW 8              // neighbors per warp
#define INV_SIGMA 10.0f

typedef unsigned long long u64;

// ---- packed f32x2 helpers (sm_103a) ----
__device__ __forceinline__ u64 pack2(float lo, float hi) {
    u64 r; asm("mov.b64 %0, {%1, %2};" : "=l"(r) : "f"(lo), "f"(hi)); return r;
}
__device__ __forceinline__ void unpack2(u64 a, float& lo, float& hi) {
    asm("mov.b64 {%0, %1}, %2;" : "=f"(lo), "=f"(hi) : "l"(a));
}
__device__ __forceinline__ u64 add2(u64 a, u64 b) {
    u64 r; asm("add.rn.f32x2 %0, %1, %2;" : "=l"(r) : "l"(a), "l"(b)); return r;
}
__device__ __forceinline__ u64 mul2(u64 a, u64 b) {
    u64 r; asm("mul.rn.f32x2 %0, %1, %2;" : "=l"(r) : "l"(a), "l"(b)); return r;
}
__device__ __forceinline__ u64 fma2(u64 a, u64 b, u64 c) {
    u64 r; asm("fma.rn.f32x2 %0, %1, %2, %3;" : "=l"(r) : "l"(a), "l"(b), "l"(c)); return r;
}

// X rows: keep resident in L2 via createpolicy + cache_hint (legal on v4.f32).
__device__ __forceinline__ float4 ldg_keep(const void* p, u64 pol) {
    float4 r;
    asm("ld.global.nc.L2::cache_hint.v4.f32 {%0,%1,%2,%3}, [%4], %5;"
        : "=f"(r.x), "=f"(r.y), "=f"(r.z), "=f"(r.w) : "l"(p), "l"(pol));
    return r;
}

// Butterfly reduce-scatter of 8 per-lane values over 32 lanes: 9 shuffles.
// On return every lane's vals[0] holds the warp total of value index
//   j = ((lane>>4)&1)<<2 | ((lane>>3)&1)<<1 | ((lane>>2)&1).
__device__ __forceinline__ float butterfly8(float* vals, int lane) {
    if (lane & 16) {
        #pragma unroll
        for (int i = 0; i < 4; ++i) { float t = vals[i]; vals[i] = vals[i + 4]; vals[i + 4] = t; }
    }
    #pragma unroll
    for (int i = 0; i < 4; ++i) vals[i] += __shfl_xor_sync(0xffffffffu, vals[i + 4], 16);
    if (lane & 8) {
        #pragma unroll
        for (int i = 0; i < 2; ++i) { float t = vals[i]; vals[i] = vals[i + 2]; vals[i + 2] = t; }
    }
    #pragma unroll
    for (int i = 0; i < 2; ++i) vals[i] += __shfl_xor_sync(0xffffffffu, vals[i + 2], 8);
    if (lane & 4) { float t = vals[0]; vals[0] = vals[1]; vals[1] = t; }
    vals[0] += __shfl_xor_sync(0xffffffffu, vals[1], 4);
    vals[0] += __shfl_xor_sync(0xffffffffu, vals[0], 2);
    vals[0] += __shfl_xor_sync(0xffffffffu, vals[0], 1);
    return vals[0];
}

__global__ __launch_bounds__(NTHREADS, 10)
void nc_kernel(const float* __restrict__ x,
               const float* __restrict__ v,
               const void*  __restrict__ kidx,
               const float* __restrict__ X,
               float* __restrict__ out)
{
    __shared__ float s_part[NWARPS][Gdim];   // 2 KB cross-warp partials
    __shared__ float s_num[Cdim];
    __shared__ float s_d2[Cdim];
    __shared__ float s_rvn;                  // 1/||v||, from warp 0

    const int row  = blockIdx.x;
    const int tid  = threadIdx.x;
    const int wid  = tid >> 5;
    const int lane = tid & 31;

    // L2 evict_last policy for X gathers.
    u64 pol;
    asm("createpolicy.fractional.L2::evict_last.b64 %0, 1.0;" : "=l"(pol));

    // Inline dtype detection: first 64B of k (one cached line, warp-uniform).
    // If k is int64 (LE, values < 200000), words 1,3,..,15 are all zero.
    int k64;
    {
        const unsigned int w0 = reinterpret_cast<const unsigned int*>(kidx)[lane & 15];
        const unsigned int nz = __ballot_sync(0xffffffffu, (lane < 16) && (lane & 1) && (w0 != 0u));
        k64 = (nz == 0u);
    }

    // Issue k-index loads FIRST (head of the critical chain k -> off -> gather).
    unsigned int off[NPW];
    if (k64) {
        const longlong2* kp = reinterpret_cast<const longlong2*>(
            reinterpret_cast<const long long*>(kidx) + (size_t)row * Cdim + wid * NPW);
        longlong2 p0 = kp[0], p1 = kp[1], p2 = kp[2], p3 = kp[3];
        off[0] = (unsigned int)p0.x << 9; off[1] = (unsigned int)p0.y << 9;
        off[2] = (unsigned int)p1.x << 9; off[3] = (unsigned int)p1.y << 9;
        off[4] = (unsigned int)p2.x << 9; off[5] = (unsigned int)p2.y << 9;
        off[6] = (unsigned int)p3.x << 9; off[7] = (unsigned int)p3.y << 9;
    } else {
        const int4* kp = reinterpret_cast<const int4*>(
            reinterpret_cast<const int*>(kidx) + (size_t)row * Cdim + wid * NPW);
        const int4 a = kp[0], b = kp[1];
        off[0] = (unsigned int)a.x << 9; off[1] = (unsigned int)a.y << 9;
        off[2] = (unsigned int)a.z << 9; off[3] = (unsigned int)a.w << 9;
        off[4] = (unsigned int)b.x << 9; off[5] = (unsigned int)b.y << 9;
        off[6] = (unsigned int)b.z << 9; off[7] = (unsigned int)b.w << 9;
    }

    // x,v rows: streaming loads (ld.global.cs) — read once, evict first.
    const float4 xv = __ldcs(reinterpret_cast<const float4*>(x + (size_t)row * Gdim) + lane);
    const float4 vv = __ldcs(reinterpret_cast<const float4*>(v + (size_t)row * Gdim) + lane);

    const u64 v01  = pack2(vv.x, vv.y), v23  = pack2(vv.z, vv.w);
    const u64 nx01 = pack2(-xv.x, -xv.y), nx23 = pack2(-xv.z, -xv.w);

    // 1/||v|| in warp 0 only; published via smem through the barrier below.
    if (wid == 0) {
        float ss = vv.x * vv.x + vv.y * vv.y + vv.z * vv.z + vv.w * vv.w;
        #pragma unroll
        for (int o = 16; o; o >>= 1)
            ss += __shfl_xor_sync(0xffffffffu, ss, o);
        if (lane == 0) s_rvn = rsqrtf(ss);
    }

    // Issue all 8 gather row loads (MLP=8, evict_last so X stays in L2).
    const char* Xb = reinterpret_cast<const char*>(X);
    u64 d01[NPW], d23[NPW];
    {
        float4 Xl[NPW];
        #pragma unroll
        for (int j = 0; j < NPW; ++j)
            Xl[j] = ldg_keep(Xb + off[j] + (lane << 4), pol);
        #pragma unroll
        for (int j = 0; j < NPW; ++j) {
            d01[j] = add2(pack2(Xl[j].x, Xl[j].y), nx01);
            d23[j] = add2(pack2(Xl[j].z, Xl[j].w), nx23);
        }
    }

    // Pass 1: num_j = dot(v, delta_j), butterfly, publish.
    {
        float nums[NPW];
        #pragma unroll
        for (int j = 0; j < NPW; ++j) {
            u64 p = fma2(d23[j], v23, mul2(d01[j], v01));
            float lo, hi; unpack2(p, lo, hi);
            nums[j] = lo + hi;
        }
        const float r = butterfly8(nums, lane);
        if ((lane & 3) == 0) {
            const int j = (((lane >> 4) & 1) << 2) | (((lane >> 3) & 1) << 1) | ((lane >> 2) & 1);
            s_num[wid * NPW + j] = r;
        }
    }
    // Pass 2: d2_j = ||delta_j||^2, butterfly, publish.
    {
        float d2s[NPW];
        #pragma unroll
        for (int j = 0; j < NPW; ++j) {
            u64 q = fma2(d23[j], d23[j], mul2(d01[j], d01[j]));
            float lo, hi; unpack2(q, lo, hi);
            d2s[j] = lo + hi;
        }
        const float r = butterfly8(d2s, lane);
        if ((lane & 3) == 0) {
            const int j = (((lane >> 4) & 1) << 2) | (((lane >> 3) & 1) << 1) | ((lane >> 2) & 1);
            s_d2[wid * NPW + j] = r;
        }
    }
    __syncthreads();

    // Weights, redundantly per warp (lane l = neighbor l), fast math.
    float wl;
    {
        const float d2 = fmaxf(s_d2[lane], 1e-24f);
        const float cs = s_num[lane] * rsqrtf(d2) * s_rvn;
        const float tv = __expf(cs * INV_SIGMA) - 1.0f;
        // reduce-scatter of (sum|tv|, sum tv): 6 shuffles + 1 exchange.
        const float sa = fabsf(tv);
        float keep = (lane & 16) ? tv : sa;
        float send = (lane & 16) ? sa : tv;
        keep += __shfl_xor_sync(0xffffffffu, send, 16);
        keep += __shfl_xor_sync(0xffffffffu, keep, 8);
        keep += __shfl_xor_sync(0xffffffffu, keep, 4);
        keep += __shfl_xor_sync(0xffffffffu, keep, 2);
        keep += __shfl_xor_sync(0xffffffffu, keep, 1);
        const float other = __shfl_xor_sync(0xffffffffu, keep, 16);
        const float sa_t = (lane & 16) ? other : keep;
        const float st_t = (lane & 16) ? keep  : other;
        wl = (tv - st_t * (1.0f / (float)Cdim)) * __fdividef(1.0f, sa_t);
    }

    // Warp partial: sum_j w_j * delta_j  (packed FMA, regs -> smem)
    {
        u64 acc01 = 0ull, acc23 = 0ull;
        #pragma unroll
        for (int j = 0; j < NPW; ++j) {
            const float wj = __shfl_sync(0xffffffffu, wl, wid * NPW + j);
            const u64 w2 = pack2(wj, wj);
            acc01 = fma2(w2, d01[j], acc01);
            acc23 = fma2(w2, d23[j], acc23);
        }
        float4 a;
        unpack2(acc01, a.x, a.y);
        unpack2(acc23, a.z, a.w);
        reinterpret_cast<float4*>(s_part[wid])[lane] = a;
    }
    __syncthreads();

    // Reduce 4 warp partials (128 threads, one g each), streaming store.
    {
        float r = (s_part[0][tid] + s_part[1][tid]) + (s_part[2][tid] + s_part[3][tid]);
        __stcs(out + (size_t)row * Gdim + tid, r);
    }
}

extern "C" void kernel_launch(void* const* d_in, const int* in_sizes, int n_in,
                              void* d_out, int out_size) {
    const float* x = (const float*)d_in[0];
    const float* v = (const float*)d_in[1];
    const void*  k = d_in[2];
    const float* X = (const float*)d_in[3];
    float* out = (float*)d_out;

    const int n = in_sizes[0] / Gdim;   // 16384

    nc_kernel<<<n, NTHREADS>>>(x, v, k, X, out);
}